// round 3
// baseline (speedup 1.0000x reference)
#include <cuda_runtime.h>
#include <cstddef>

// Problem constants (fixed by the reference setup)
#define BATCH 32
#define SEQ   512
#define DIM   1024
#define NCOLS (BATCH * DIM)   // 32768 independent columns
#define PF 16                 // software-pipeline depth (register ring buffer)

// 1.0f / 0.001f correctly rounded = 999.99994f; for sp in {0,1} multiplying by
// this is bitwise identical to dividing by 0.001f (the reference's spikes/DT).
#define INV_DT (1.0f / 0.001f)

// One scan step = 4 substeps of {v += r; sp = floor(v); v -= sp;}, bitwise-
// faithful. With v in [0,1) and 0 <= r < 1:  a = v + r lies in [0, 2), so
//   floor(a)     == (a >= 1.0f) ? 1.0f : 0.0f
//   a - floor(a) == (a >= 1.0f) ? a - 1.0f : a      (Sterbenz: a-1 exact)
// Only the LAST substep's spike survives (the reference overwrites it each
// substep), so substeps 0-2 update v only.
__device__ __forceinline__ float step4(float& v, float r)
{
    #pragma unroll
    for (int i = 0; i < 3; ++i) {
        const float a  = v + r;
        const float am = a - 1.0f;          // off the compare path
        v = (a >= 1.0f) ? am : a;
    }
    const float a  = v + r;
    const float am = a - 1.0f;
    const bool  h  = (a >= 1.0f);
    v = h ? am : a;
    return h ? 1.0f : 0.0f;
}

__global__ __launch_bounds__(256)
void dual_threshold_scan_kernel(const float* __restrict__ inputs,
                                const float* __restrict__ init_state,
                                float* __restrict__ out)
{
    // grid 128 x block 256 = exactly NCOLS threads: no guard, one wave,
    // one block per SM (148 SMs), zero wave imbalance.
    const int col = blockIdx.x * blockDim.x + threadIdx.x;

    const int b = col >> 10;          // col / DIM
    const int d = col & (DIM - 1);    // col % DIM

    const size_t base = (size_t)b * SEQ * DIM + d;
    const float* __restrict__ ip = inputs + base;
    float*       __restrict__ op = out + base;

    float v = init_state[col];

    // Prologue: fill the 16-deep register pipeline.
    float buf[PF];
    #pragma unroll
    for (int j = 0; j < PF; ++j)
        buf[j] = __ldcs(ip + (size_t)j * DIM);

    // Main loop: consume chunk k while prefetching chunk k+1. Loads are
    // independent of the v-chain; consumed PF steps (~768 cyc) after issue,
    // which fully covers DRAM latency.
    for (int s0 = 0; s0 < SEQ - PF; s0 += PF) {
        #pragma unroll
        for (int j = 0; j < PF; ++j) {
            const float x = buf[j];
            buf[j] = __ldcs(ip + (size_t)(s0 + PF + j) * DIM);  // prefetch
            const float r  = fmaxf(x, 0.0f) * 0.001f;           // relu * DT
            const float sp = step4(v, r);
            __stcs(op + (size_t)(s0 + j) * DIM, sp * INV_DT);
        }
    }

    // Epilogue: last chunk, no prefetch.
    {
        const int s0 = SEQ - PF;
        #pragma unroll
        for (int j = 0; j < PF; ++j) {
            const float x  = buf[j];
            const float r  = fmaxf(x, 0.0f) * 0.001f;
            const float sp = step4(v, r);
            __stcs(op + (size_t)(s0 + j) * DIM, sp * INV_DT);
        }
    }
}

extern "C" void kernel_launch(void* const* d_in, const int* in_sizes, int n_in,
                              void* d_out, int out_size)
{
    const float* inputs     = (const float*)d_in[0];  // [32, 512, 1024] f32
    const float* init_state = (const float*)d_in[1];  // [32, 1024] f32
    float*       out        = (float*)d_out;          // [32, 512, 1024] f32

    (void)in_sizes; (void)n_in; (void)out_size;

    dual_threshold_scan_kernel<<<128, 256>>>(inputs, init_state, out);
}

// round 5
// speedup vs baseline: 1.1213x; 1.1213x over previous
#include <cuda_runtime.h>
#include <cstddef>

// Problem constants (fixed by the reference setup)
#define BATCH 32
#define SEQ   512
#define DIM   1024
#define NCOLS (BATCH * DIM)   // 32768 independent columns
#define PF 32                 // software-pipeline depth (register ring buffer)

// 1.0f / 0.001f correctly rounded = 999.99994f. For sp in {0,1},
// sp / 0.001f == sp * 999.99994f == (sp ? 999.99994f : 0.0f) bitwise.
#define SPIKE_OUT 999.99994f

// One scan step = 4 substeps of {v += r; sp = floor(v); v -= sp;}, bitwise-
// faithful. With v in [0,1) and 0 <= r < 1:  a = v + r lies in [0, 2), so
//   floor(a)     == (a >= 1.0f) ? 1.0f : 0.0f
//   a - floor(a) == (a >= 1.0f) ? a - 1.0f : a      (Sterbenz: a-1.0f exact)
// Only the LAST substep's spike survives (the reference overwrites spikes
// each substep), so substeps 0-2 update v only. Returns the already-scaled
// output value (spike / DT).
__device__ __forceinline__ float step4(float& v, float r)
{
    #pragma unroll
    for (int i = 0; i < 3; ++i) {
        const float a  = v + r;
        const float am = a - 1.0f;          // off the compare path
        v = (a >= 1.0f) ? am : a;
    }
    const float a  = v + r;
    const float am = a - 1.0f;
    const bool  h  = (a >= 1.0f);
    v = h ? am : a;
    return h ? SPIKE_OUT : 0.0f;
}

__global__ __launch_bounds__(256, 1)
void dual_threshold_scan_kernel(const float* __restrict__ inputs,
                                const float* __restrict__ init_state,
                                float* __restrict__ out)
{
    // grid 128 x block 256 = exactly NCOLS threads: no guard, one wave.
    const int col = blockIdx.x * blockDim.x + threadIdx.x;

    const int b = col >> 10;          // col / DIM
    const int d = col & (DIM - 1);    // col % DIM

    const size_t base = (size_t)b * SEQ * DIM + d;
    const float* __restrict__ ip = inputs + base;
    float*       __restrict__ op = out + base;

    float v = init_state[col];

    // Prologue: fill the 32-deep register pipeline. 128 B outstanding per
    // thread x 32768 threads = 4 MB in flight chip-wide — enough to cover
    // queued DRAM latency at multi-TB/s.
    float buf[PF];
    #pragma unroll
    for (int j = 0; j < PF; ++j)
        buf[j] = __ldcs(ip + (size_t)j * DIM);

    // Main loop: consume chunk k while prefetching chunk k+1. Loads are
    // independent of the v-chain; each load is consumed PF steps after issue.
    for (int s0 = 0; s0 < SEQ - PF; s0 += PF) {
        #pragma unroll
        for (int j = 0; j < PF; ++j) {
            const float x = buf[j];
            buf[j] = __ldcs(ip + (size_t)(s0 + PF + j) * DIM);  // prefetch
            const float r = fmaxf(x, 0.0f) * 0.001f;            // relu * DT
            __stcs(op + (size_t)(s0 + j) * DIM, step4(v, r));
        }
    }

    // Epilogue: last chunk, no prefetch.
    {
        const int s0 = SEQ - PF;
        #pragma unroll
        for (int j = 0; j < PF; ++j) {
            const float r = fmaxf(buf[j], 0.0f) * 0.001f;
            __stcs(op + (size_t)(s0 + j) * DIM, step4(v, r));
        }
    }
}

extern "C" void kernel_launch(void* const* d_in, const int* in_sizes, int n_in,
                              void* d_out, int out_size)
{
    const float* inputs     = (const float*)d_in[0];  // [32, 512, 1024] f32
    const float* init_state = (const float*)d_in[1];  // [32, 1024] f32
    float*       out        = (float*)d_out;          // [32, 512, 1024] f32

    (void)in_sizes; (void)n_in; (void)out_size;

    dual_threshold_scan_kernel<<<128, 256>>>(inputs, init_state, out);
}

// round 7
// speedup vs baseline: 1.3975x; 1.2463x over previous
#include <cuda_runtime.h>
#include <cstddef>
#include <cstdint>

// Problem constants (fixed by the reference setup)
#define BATCH 32
#define SEQ   512
#define DIM   1024
#define NCOLS (BATCH * DIM)   // 32768 independent columns
#define CHUNK 8               // scan steps per pipeline stage
#define STAGES 5              // smem ring depth (40 KB)
#define NCHUNK (SEQ / CHUNK)  // 64

// 1.0f / 0.001f correctly rounded = 999.99994f. For sp in {0,1},
// sp / 0.001f == (sp ? 999.99994f : 0.0f) bitwise.
#define SPIKE_OUT 999.99994f

// One scan step = 4 substeps of {v += r; sp = floor(v); v -= sp;}, bitwise-
// faithful. With v in [0,1) and 0 <= r < 1:  a = v + r lies in [0, 2), so
//   floor(a)     == (a >= 1.0f) ? 1.0f : 0.0f
//   a - floor(a) == (a >= 1.0f) ? a - 1.0f : a      (Sterbenz: a-1.0f exact)
// Only the LAST substep's spike survives. Returns spike / DT.
__device__ __forceinline__ float step4(float& v, float r)
{
    #pragma unroll
    for (int i = 0; i < 3; ++i) {
        const float a  = v + r;
        const float am = a - 1.0f;          // off the compare path
        v = (a >= 1.0f) ? am : a;
    }
    const float a  = v + r;
    const float am = a - 1.0f;
    const bool  h  = (a >= 1.0f);
    v = h ? am : a;
    return h ? SPIKE_OUT : 0.0f;
}

__global__ __launch_bounds__(256, 1)
void dual_threshold_scan_kernel(const float* __restrict__ inputs,
                                const float* __restrict__ init_state,
                                float* __restrict__ out)
{
    // Ring of input tiles: stage -> CHUNK rows x 256 cols (this block's slice).
    __shared__ float stage_buf[STAGES][CHUNK][256];

    const int tid = threadIdx.x;
    const int col = blockIdx.x * 256 + tid;      // grid 128 x 256 == NCOLS

    // Block-uniform coordinates: 4 blocks per batch row.
    const int b_blk = blockIdx.x >> 2;           // batch index
    const int d0    = (blockIdx.x & 3) * 256;    // first dim col of this block

    // Fetch role: 2 x 16B cp.async per thread per chunk.
    // Round r covers rows {0..3}+4r; thread t fetches row (t>>6)+4r,
    // float cols [(t&63)*4, +4) of this block's 256-col slice.
    const int frow  = tid >> 6;                  // 0..3
    const int fcol4 = (tid & 63) * 4;            // 16B-aligned float offset
    const float* fsrc = inputs + (size_t)b_blk * SEQ * DIM + d0 + fcol4;

    // Issue one chunk's loads as one commit group.
    auto issue_chunk = [&](int c) {
        const int st = c % STAGES;
        #pragma unroll
        for (int r = 0; r < 2; ++r) {
            const float* g = fsrc + (size_t)(c * CHUNK + frow + 4 * r) * DIM;
            uint32_t s = (uint32_t)__cvta_generic_to_shared(
                &stage_buf[st][frow + 4 * r][fcol4]);
            asm volatile("cp.async.cg.shared.global [%0], [%1], 16;"
                         :: "r"(s), "l"(g));
        }
        asm volatile("cp.async.commit_group;" ::: "memory");
    };

    // Prologue: groups for chunks 0..STAGES-2 in flight.
    #pragma unroll
    for (int c = 0; c < STAGES - 1; ++c)
        issue_chunk(c);

    const size_t base = (size_t)b_blk * SEQ * DIM + d0 + tid;
    float* __restrict__ op = out + base;

    float v = init_state[col];

    for (int k = 0; k < NCHUNK; ++k) {
        // Groups issued so far: chunks 0..k+STAGES-2 (prologue + end of iters
        // 0..k-1). Allowing STAGES-2 pending completes chunk k's group (FIFO).
        asm volatile("cp.async.wait_group %0;" :: "n"(STAGES - 2) : "memory");
        __syncthreads();   // publish smem writes; all threads past chunk k-1 reads

        // Compute chunk k from its stage.
        const int st = k % STAGES;
        #pragma unroll
        for (int j = 0; j < CHUNK; ++j) {
            const float x = stage_buf[st][j][tid];
            const float r = fmaxf(x, 0.0f) * 0.001f;        // relu * DT
            __stcs(op + (size_t)(k * CHUNK + j) * DIM, step4(v, r));
        }

        // Refill: chunk k+STAGES-1 overwrites the stage read in iter k-1
        // (safe: the barrier above ensured everyone finished it). Empty
        // commit groups in the tail keep the wait_group arithmetic exact.
        const int kn = k + STAGES - 1;
        if (kn < NCHUNK) issue_chunk(kn);
        else asm volatile("cp.async.commit_group;" ::: "memory");
    }
}

extern "C" void kernel_launch(void* const* d_in, const int* in_sizes, int n_in,
                              void* d_out, int out_size)
{
    const float* inputs     = (const float*)d_in[0];  // [32, 512, 1024] f32
    const float* init_state = (const float*)d_in[1];  // [32, 1024] f32
    float*       out        = (float*)d_out;          // [32, 512, 1024] f32

    (void)in_sizes; (void)n_in; (void)out_size;

    dual_threshold_scan_kernel<<<128, 256>>>(inputs, init_state, out);
}

// round 8
// speedup vs baseline: 1.5564x; 1.1137x over previous
#include <cuda_runtime.h>
#include <cstddef>
#include <cstdint>

// Problem constants (fixed by the reference setup)
#define BATCH 32
#define SEQ   512
#define DIM   1024
#define NCOLS (BATCH * DIM)   // 32768 independent columns
#define CHUNK 16              // scan steps per pipeline stage
#define STAGES 3              // smem ring depth (3 x 16 x 1KB = 48 KB)
#define NCHUNK (SEQ / CHUNK)  // 32

// 1.0f / 0.001f correctly rounded = 999.99994f. For sp in {0,1},
// sp / 0.001f == sp * 999.99994f bitwise (1*c and 0*c are exact).
#define SPIKE_OUT 999.99994f

// floor(a) for a in [0,2) as a float-valued compare: FSET emits 1.0f/0.0f in
// a float register — fixed-lat 4, NO predicate (avoids the 13-cyc
// pred-as-guard path ptxas produces for ternaries).
__device__ __forceinline__ float ge1(float a)
{
    float one;
    asm("set.ge.f32.f32 %0, %1, %2;" : "=f"(one) : "f"(a), "f"(1.0f));
    return one;
}

// One scan step = 4 substeps of {v += r; sp = floor(v); v -= sp;}, bitwise-
// faithful. With v in [0,1) and 0 <= r < 1:  a = v + r lies in [0, 2), so
// floor(a) == ge1(a) in {0.0f, 1.0f}, and v' = a - ge1(a) is the literal
// reference subtraction. Chain: FADD(4) -> FSET(4) -> FADD(4) per substep.
// Only the LAST substep's spike survives. Returns spike / DT.
__device__ __forceinline__ float step4(float& v, float r)
{
    #pragma unroll
    for (int i = 0; i < 3; ++i) {
        const float a = v + r;
        v = a - ge1(a);
    }
    const float a   = v + r;
    const float one = ge1(a);
    v = a - one;
    return one * SPIKE_OUT;      // off the chain
}

__global__ __launch_bounds__(256, 1)
void dual_threshold_scan_kernel(const float* __restrict__ inputs,
                                const float* __restrict__ init_state,
                                float* __restrict__ out)
{
    // Ring of input tiles: stage -> CHUNK rows x 256 cols (this block's slice).
    __shared__ float stage_buf[STAGES][CHUNK][256];   // 49152 B (static cap)

    const int tid = threadIdx.x;
    const int col = blockIdx.x * 256 + tid;      // grid 128 x 256 == NCOLS

    // Block-uniform coordinates: 4 blocks per batch row.
    const int b_blk = blockIdx.x >> 2;           // batch index
    const int d0    = (blockIdx.x & 3) * 256;    // first dim col of this block

    // Fetch role: 4 x 16B cp.async per thread per chunk.
    // Round r covers rows (tid>>6) + 4r (r=0..3 -> rows 0..15), float cols
    // [(tid&63)*4, +4) of this block's 256-col slice.
    const int frow  = tid >> 6;                  // 0..3
    const int fcol4 = (tid & 63) * 4;            // 16B-aligned float offset
    const float* fsrc = inputs + (size_t)b_blk * SEQ * DIM + d0 + fcol4;

    // Issue one chunk's loads as one commit group.
    auto issue_chunk = [&](int c) {
        const int st = c % STAGES;
        #pragma unroll
        for (int r = 0; r < 4; ++r) {
            const float* g = fsrc + (size_t)(c * CHUNK + frow + 4 * r) * DIM;
            uint32_t s = (uint32_t)__cvta_generic_to_shared(
                &stage_buf[st][frow + 4 * r][fcol4]);
            asm volatile("cp.async.cg.shared.global [%0], [%1], 16;"
                         :: "r"(s), "l"(g));
        }
        asm volatile("cp.async.commit_group;" ::: "memory");
    };

    // Prologue: groups for chunks 0..STAGES-2 in flight (32-step lookahead).
    #pragma unroll
    for (int c = 0; c < STAGES - 1; ++c)
        issue_chunk(c);

    const size_t base = (size_t)b_blk * SEQ * DIM + d0 + tid;
    float* __restrict__ op = out + base;

    float v = init_state[col];

    for (int k = 0; k < NCHUNK; ++k) {
        // Issued so far: chunks 0..k+STAGES-2. Allowing STAGES-2 pending
        // groups forces chunk k's group complete (FIFO).
        asm volatile("cp.async.wait_group %0;" :: "n"(STAGES - 2) : "memory");
        __syncthreads();   // publish smem writes across threads

        // Compute chunk k from its stage.
        const int st = k % STAGES;
        #pragma unroll
        for (int j = 0; j < CHUNK; ++j) {
            const float x = stage_buf[st][j][tid];
            const float r = fmaxf(x, 0.0f) * 0.001f;        // relu * DT
            __stcs(op + (size_t)(k * CHUNK + j) * DIM, step4(v, r));
        }

        // Refill: chunk k+STAGES-1 overwrites the stage read in iter k-1
        // (the barrier above ordered those reads first). Empty commit groups
        // in the tail keep the wait_group arithmetic exact.
        const int kn = k + STAGES - 1;
        if (kn < NCHUNK) issue_chunk(kn);
        else asm volatile("cp.async.commit_group;" ::: "memory");
    }
}

extern "C" void kernel_launch(void* const* d_in, const int* in_sizes, int n_in,
                              void* d_out, int out_size)
{
    const float* inputs     = (const float*)d_in[0];  // [32, 512, 1024] f32
    const float* init_state = (const float*)d_in[1];  // [32, 1024] f32
    float*       out        = (float*)d_out;          // [32, 512, 1024] f32

    (void)in_sizes; (void)n_in; (void)out_size;

    dual_threshold_scan_kernel<<<128, 256>>>(inputs, init_state, out);
}